// round 1
// baseline (speedup 1.0000x reference)
#include <cuda_runtime.h>
#include <math.h>

#define HW   65536
#define IMG  6291456          // 96*65536
#define NPIX 25165824         // 4*96*65536
#define SCALE 0.17677669529663687f   // 32^-0.5

static __device__ float g_V[NPIX];
static __device__ float g_aV[NPIX];
static __device__ float g_attn[NPIX];
static __device__ float g_bias[3*64*64];

// ---------------------------------------------------------------------------
// K1: relative-position bias MLP.  bias[h][i][j], i,j in [0,64)
// ---------------------------------------------------------------------------
__device__ __forceinline__ float sgnlog(int d) {
    float a = fabsf((float)d);
    float l = log1pf(a);
    return d < 0 ? -l : l;
}

__global__ void bias_kernel(const float* __restrict__ mw1, const float* __restrict__ mb1,
                            const float* __restrict__ mw2, const float* __restrict__ mb2) {
    int t = blockIdx.x * 256 + threadIdx.x;
    if (t >= 4096) return;
    int i = t >> 6, j = t & 63;
    float r0 = sgnlog((i >> 3) - (j >> 3));
    float r1 = sgnlog((i & 7) - (j & 7));
    float a0 = 0.f, a1 = 0.f, a2 = 0.f;
    for (int h = 0; h < 256; h++) {
        float hid = fmaf(r0, mw1[h], fmaf(r1, mw1[256 + h], mb1[h]));
        hid = fmaxf(hid, 0.f);
        a0 = fmaf(hid, mw2[h * 3 + 0], a0);
        a1 = fmaf(hid, mw2[h * 3 + 1], a1);
        a2 = fmaf(hid, mw2[h * 3 + 2], a2);
    }
    g_bias[t]        = a0 + mb2[0];
    g_bias[4096 + t] = a1 + mb2[1];
    g_bias[8192 + t] = a2 + mb2[2];
}

// ---------------------------------------------------------------------------
// K2: conv1x1 96->96 for V (z=0, vision) and aV (z=1, ass_vision)
// block = 256 threads, tile = 96 c_out x 128 pixels
// smem: s_in[96][129] + s_w[96][97] + s_b[96]  = 87168 B
// ---------------------------------------------------------------------------
__global__ __launch_bounds__(256, 2)
void conv_v_kernel(const float* __restrict__ vis, const float* __restrict__ avis,
                   const float* __restrict__ wv, const float* __restrict__ bv,
                   const float* __restrict__ wav, const float* __restrict__ bav) {
    extern __shared__ float sm[];
    float* s_in = sm;                  // 96*129 = 12384
    float* s_w  = sm + 12384;          // 96*97  =  9312
    float* s_b  = sm + 12384 + 9312;   // 96
    const float *in, *w, *bb;
    float* out;
    if (blockIdx.z == 0) { in = vis;  w = wv;  bb = bv;  out = g_V;  }
    else                 { in = avis; w = wav; bb = bav; out = g_aV; }
    int tid = threadIdx.x;
    int base = (blockIdx.x >> 9) * IMG + (blockIdx.x & 511) * 128;

    for (int l = tid; l < 9216; l += 256) s_w[(l / 96) * 97 + (l % 96)] = w[l];
    if (tid < 96) s_b[tid] = bb[tid];
    for (int l = tid; l < 12288; l += 256) {
        int c = l >> 7, p = l & 127;
        s_in[c * 129 + p] = in[base + c * HW + p];
    }
    __syncthreads();

    int og = tid >> 3, pg = tid & 7;   // o = og + 32u (u<3), p = pg + 8v (v<16)
    float acc[3][16];
    #pragma unroll
    for (int u = 0; u < 3; u++)
        #pragma unroll
        for (int v = 0; v < 16; v++) acc[u][v] = 0.f;

    for (int c = 0; c < 96; c++) {
        float wf[3], pf[16];
        #pragma unroll
        for (int u = 0; u < 3; u++) wf[u] = s_w[(og + 32 * u) * 97 + c];
        #pragma unroll
        for (int v = 0; v < 16; v++) pf[v] = s_in[c * 129 + pg + 8 * v];
        #pragma unroll
        for (int u = 0; u < 3; u++)
            #pragma unroll
            for (int v = 0; v < 16; v++) acc[u][v] = fmaf(wf[u], pf[v], acc[u][v]);
    }
    #pragma unroll
    for (int u = 0; u < 3; u++) {
        int o = og + 32 * u;
        float bo = s_b[o];
        #pragma unroll
        for (int v = 0; v < 16; v++)
            out[base + o * HW + pg + 8 * v] = acc[u][v] + bo;
    }
}

// ---------------------------------------------------------------------------
// K3: per-window fused QK projection + window attention.
// One block per window (4096 blocks), 256 threads.
// smem: s_w[192][97] + s_a[64][97] + s_qk[64][193] + s_s[3][64][65] = 198656 B
// ---------------------------------------------------------------------------
__global__ __launch_bounds__(256, 1)
void attn_kernel(const float* __restrict__ vision,
                 const float* __restrict__ wqk, const float* __restrict__ bqk) {
    extern __shared__ float sm[];
    float* s_w  = sm;                      // 192*97 = 18624
    float* s_a  = sm + 18624;              // 64*97  =  6208
    float* s_qk = sm + 18624 + 6208;       // 64*193 = 12352
    float* s_s  = sm + 18624 + 6208 + 12352; // 3*64*65 = 12480
    int tid = threadIdx.x;
    int blk = blockIdx.x;
    int b  = blk >> 10;
    int wy = (blk >> 5) & 31, wx = blk & 31;
    int pixbase = b * IMG + (wy * 8) * 256 + wx * 8;  // + c*HW + r*256 + col

    // load wqk [192][96] -> pitch 97
    for (int l = tid; l < 18432; l += 256) s_w[(l / 96) * 97 + (l % 96)] = wqk[l];
    // load input window [n=64][c=96] -> pitch 97
    for (int l = tid; l < 6144; l += 256) {
        int c = l >> 6, n = l & 63;
        s_a[n * 97 + c] = vision[pixbase + c * HW + (n >> 3) * 256 + (n & 7)];
    }
    __syncthreads();

    // ---- QK GEMM: s_qk[n][o] = sum_c s_a[n][c]*wqk[o][c] + bqk[o]  (scale Q) ----
    {
        int og = tid >> 3, ng = tid & 7;    // o = og + 32u (u<6), n = ng + 8v (v<8)
        float acc[6][8];
        #pragma unroll
        for (int u = 0; u < 6; u++)
            #pragma unroll
            for (int v = 0; v < 8; v++) acc[u][v] = 0.f;
        for (int c = 0; c < 96; c++) {
            float wf[6], af[8];
            #pragma unroll
            for (int u = 0; u < 6; u++) wf[u] = s_w[(og + 32 * u) * 97 + c];
            #pragma unroll
            for (int v = 0; v < 8; v++) af[v] = s_a[(ng + 8 * v) * 97 + c];
            #pragma unroll
            for (int u = 0; u < 6; u++)
                #pragma unroll
                for (int v = 0; v < 8; v++) acc[u][v] = fmaf(wf[u], af[v], acc[u][v]);
        }
        #pragma unroll
        for (int u = 0; u < 6; u++) {
            int o = og + 32 * u;
            float bo = __ldg(&bqk[o]);
            float mul = (o < 96) ? SCALE : 1.0f;
            #pragma unroll
            for (int v = 0; v < 8; v++) {
                int n = ng + 8 * v;
                s_qk[n * 193 + o] = (acc[u][v] + bo) * mul;
            }
        }
    }
    __syncthreads();

    // ---- load V window into s_a (input no longer needed) ----
    for (int l = tid; l < 6144; l += 256) {
        int c = l >> 6, n = l & 63;
        s_a[n * 97 + c] = g_V[pixbase + c * HW + (n >> 3) * 256 + (n & 7)];
    }

    // ---- S = Q K^T + bias (does not touch s_a) ----
    {
        int ng2 = tid >> 4, mg = tid & 15;  // n = ng2+16i (i<4), m = mg+16j (j<4)
        for (int h = 0; h < 3; h++) {
            float acc[4][4];
            #pragma unroll
            for (int i = 0; i < 4; i++)
                #pragma unroll
                for (int j = 0; j < 4; j++) acc[i][j] = 0.f;
            for (int d = 0; d < 32; d++) {
                float qf[4], kf[4];
                #pragma unroll
                for (int i = 0; i < 4; i++) qf[i] = s_qk[(ng2 + 16 * i) * 193 + h * 32 + d];
                #pragma unroll
                for (int j = 0; j < 4; j++) kf[j] = s_qk[(mg + 16 * j) * 193 + 96 + h * 32 + d];
                #pragma unroll
                for (int i = 0; i < 4; i++)
                    #pragma unroll
                    for (int j = 0; j < 4; j++) acc[i][j] = fmaf(qf[i], kf[j], acc[i][j]);
            }
            #pragma unroll
            for (int i = 0; i < 4; i++)
                #pragma unroll
                for (int j = 0; j < 4; j++) {
                    int n = ng2 + 16 * i, m = mg + 16 * j;
                    s_s[h * 4160 + n * 65 + m] = acc[i][j] + g_bias[h * 4096 + n * 64 + m];
                }
        }
    }
    __syncthreads();

    // ---- softmax over rows (192 rows = 3 heads x 64) ----
    if (tid < 192) {
        int h = tid >> 6, n = tid & 63;
        float* row = s_s + h * 4160 + n * 65;
        float mx = row[0];
        #pragma unroll 8
        for (int m = 1; m < 64; m++) mx = fmaxf(mx, row[m]);
        float sum = 0.f;
        #pragma unroll 8
        for (int m = 0; m < 64; m++) {
            float e = __expf(row[m] - mx);
            row[m] = e;
            sum += e;
        }
        float r = 1.f / sum;
        #pragma unroll 8
        for (int m = 0; m < 64; m++) row[m] *= r;
    }
    __syncthreads();

    // ---- O = P @ V  -> staged into s_qk region (pitch 97), then coalesced store ----
    float* s_o = s_qk;
    {
        int ngr = tid >> 3, dg = tid & 7;   // n = ngr+32i (i<2), d = dg+8j (j<4)
        for (int h = 0; h < 3; h++) {
            float acc[2][4];
            #pragma unroll
            for (int i = 0; i < 2; i++)
                #pragma unroll
                for (int j = 0; j < 4; j++) acc[i][j] = 0.f;
            for (int m = 0; m < 64; m++) {
                float pf[2], vf[4];
                #pragma unroll
                for (int i = 0; i < 2; i++) pf[i] = s_s[h * 4160 + (ngr + 32 * i) * 65 + m];
                #pragma unroll
                for (int j = 0; j < 4; j++) vf[j] = s_a[m * 97 + h * 32 + dg + 8 * j];
                #pragma unroll
                for (int i = 0; i < 2; i++)
                    #pragma unroll
                    for (int j = 0; j < 4; j++) acc[i][j] = fmaf(pf[i], vf[j], acc[i][j]);
            }
            #pragma unroll
            for (int i = 0; i < 2; i++)
                #pragma unroll
                for (int j = 0; j < 4; j++)
                    s_o[(ngr + 32 * i) * 97 + h * 32 + dg + 8 * j] = acc[i][j];
        }
    }
    __syncthreads();

    for (int l = tid; l < 6144; l += 256) {
        int c = l >> 6, n = l & 63;
        g_attn[pixbase + c * HW + (n >> 3) * 256 + (n & 7)] = s_o[n * 97 + c];
    }
}

// ---------------------------------------------------------------------------
// K4: out = conv1x1( dwconv5(V) + attn , wp ) + bp   (z=0)
//     out_ass uses aV/wdwa/wpa but the SAME attn (source bug)  (z=1)
// block = 256 threads, tile = one row y, 128 pixels, all 96 channels
// ---------------------------------------------------------------------------
__global__ __launch_bounds__(256, 2)
void out_kernel(const float* __restrict__ wdw, const float* __restrict__ bdw,
                const float* __restrict__ wdwa, const float* __restrict__ bdwa,
                const float* __restrict__ wp, const float* __restrict__ bp,
                const float* __restrict__ wpa, const float* __restrict__ bpa,
                float* __restrict__ dout) {
    extern __shared__ float sm[];
    float* s_d   = sm;                         // 96*129 = 12384
    float* s_w   = sm + 12384;                 // 96*97  =  9312
    float* s_dw  = sm + 12384 + 9312;          // 96*25  =  2400
    float* s_row = sm + 12384 + 9312 + 2400;   // 2*5*133 = 1330
    float* s_b   = s_row + 1330;               // 96
    float* s_bd  = s_b + 96;                   // 96

    int z = blockIdx.z;
    const float* Vp = z ? g_aV : g_V;
    const float* wD = z ? wdwa : wdw;
    const float* bD = z ? bdwa : bdw;
    const float* wP = z ? wpa : wp;
    const float* bP = z ? bpa : bp;
    float* outp = dout + z * NPIX;

    int bx = blockIdx.x;
    int b  = bx >> 9;
    int y  = (bx >> 1) & 255;
    int x0 = (bx & 1) * 128;
    int tid = threadIdx.x;
    const float* Vb = Vp + b * IMG;
    const float* attnb = g_attn + b * IMG + y * 256 + x0;

    for (int l = tid; l < 9216; l += 256) s_w[(l / 96) * 97 + (l % 96)] = wP[l];
    for (int l = tid; l < 2400; l += 256) s_dw[l] = wD[l];
    if (tid < 96) { s_b[tid] = bP[tid]; s_bd[tid] = bD[tid]; }

    int half = tid >> 7, p = tid & 127;
    for (int cc = 0; cc < 96; cc += 2) {
        __syncthreads();   // prev compute done (and first-iter preloads visible)
        for (int l = tid; l < 1320; l += 256) {
            int hh = l / 660;
            int rem = l - hh * 660;
            int r = rem / 132, q = rem - r * 132;
            int yy = y + r - 2;  yy = yy < 0 ? -yy : (yy > 255 ? 510 - yy : yy);
            int xx = x0 - 2 + q; xx = xx < 0 ? -xx : (xx > 255 ? 510 - xx : xx);
            s_row[hh * 665 + r * 133 + q] = Vb[(cc + hh) * HW + yy * 256 + xx];
        }
        __syncthreads();
        int c = cc + half;
        const float* rb = s_row + half * 665;
        const float* wb = s_dw + c * 25;
        float sum = 0.f;
        #pragma unroll
        for (int r = 0; r < 5; r++)
            #pragma unroll
            for (int j = 0; j < 5; j++)
                sum = fmaf(rb[r * 133 + p + j], wb[r * 5 + j], sum);
        s_d[c * 129 + p] = sum + s_bd[c] + attnb[c * HW + p];
    }
    __syncthreads();

    // GEMM: out[o][p] = sum_c s_d[c][p] * wp[o][c] + bp[o]
    int og = tid >> 3, pg = tid & 7;
    float acc[3][16];
    #pragma unroll
    for (int u = 0; u < 3; u++)
        #pragma unroll
        for (int v = 0; v < 16; v++) acc[u][v] = 0.f;
    for (int c = 0; c < 96; c++) {
        float wf[3], df[16];
        #pragma unroll
        for (int u = 0; u < 3; u++) wf[u] = s_w[(og + 32 * u) * 97 + c];
        #pragma unroll
        for (int v = 0; v < 16; v++) df[v] = s_d[c * 129 + pg + 8 * v];
        #pragma unroll
        for (int u = 0; u < 3; u++)
            #pragma unroll
            for (int v = 0; v < 16; v++) acc[u][v] = fmaf(wf[u], df[v], acc[u][v]);
    }
    int obase = b * IMG + y * 256 + x0;
    #pragma unroll
    for (int u = 0; u < 3; u++) {
        int o = og + 32 * u;
        float bo = s_b[o];
        #pragma unroll
        for (int v = 0; v < 16; v++)
            outp[obase + o * HW + pg + 8 * v] = acc[u][v] + bo;
    }
}

// ---------------------------------------------------------------------------
extern "C" void kernel_launch(void* const* d_in, const int* in_sizes, int n_in,
                              void* d_out, int out_size) {
    const float* vision     = (const float*)d_in[0];
    const float* ass_vision = (const float*)d_in[1];
    const float* wv   = (const float*)d_in[2];
    const float* bv   = (const float*)d_in[3];
    const float* wav  = (const float*)d_in[4];
    const float* bav  = (const float*)d_in[5];
    const float* wqk  = (const float*)d_in[6];
    const float* bqk  = (const float*)d_in[7];
    // d_in[8], d_in[9] = waqk, baqk: dead code in reference (aaw unused)
    const float* wdw  = (const float*)d_in[10];
    const float* bdw  = (const float*)d_in[11];
    const float* wdwa = (const float*)d_in[12];
    const float* bdwa = (const float*)d_in[13];
    const float* wp   = (const float*)d_in[14];
    const float* bp   = (const float*)d_in[15];
    const float* wpa  = (const float*)d_in[16];
    const float* bpa  = (const float*)d_in[17];
    const float* mw1  = (const float*)d_in[18];
    const float* mb1  = (const float*)d_in[19];
    const float* mw2  = (const float*)d_in[20];
    const float* mb2  = (const float*)d_in[21];
    float* out = (float*)d_out;

    const int SMEM_CONV = (12384 + 9312 + 96) * 4;                 // 87168
    const int SMEM_ATTN = (18624 + 6208 + 12352 + 12480) * 4;      // 198656
    const int SMEM_OUT  = (12384 + 9312 + 2400 + 1330 + 192) * 4;  // 102472
    cudaFuncSetAttribute(conv_v_kernel, cudaFuncAttributeMaxDynamicSharedMemorySize, SMEM_CONV);
    cudaFuncSetAttribute(attn_kernel,  cudaFuncAttributeMaxDynamicSharedMemorySize, SMEM_ATTN);
    cudaFuncSetAttribute(out_kernel,   cudaFuncAttributeMaxDynamicSharedMemorySize, SMEM_OUT);

    bias_kernel<<<16, 256>>>(mw1, mb1, mw2, mb2);
    conv_v_kernel<<<dim3(2048, 1, 2), 256, SMEM_CONV>>>(vision, ass_vision, wv, bv, wav, bav);
    attn_kernel<<<4096, 256, SMEM_ATTN>>>(vision, wqk, bqk);
    out_kernel<<<dim3(2048, 1, 2), 256, SMEM_OUT>>>(wdw, bdw, wdwa, bdwa, wp, bp, wpa, bpa, out);
}

// round 2
// speedup vs baseline: 2.3429x; 2.3429x over previous
#include <cuda_runtime.h>
#include <math.h>

#define HW   65536
#define IMG  6291456          // 96*65536
#define NPIX 25165824         // 4*96*65536
#define SCALE 0.17677669529663687f

typedef unsigned long long ull;

static __device__ __align__(16) float g_V[NPIX];
static __device__ __align__(16) float g_aV[NPIX];
static __device__ __align__(16) float g_Q[NPIX];
static __device__ __align__(16) float g_K[NPIX];
static __device__ __align__(16) float g_attn[NPIX];
static __device__ __align__(16) float g_D[2 * NPIX];
static __device__ __align__(16) float g_bias[3 * 64 * 64];

// ---- f32x2 packed helpers (64-bit carriers) --------------------------------
__device__ __forceinline__ ull pk(float x) {
    ull r; asm("mov.b64 %0, {%1, %1};" : "=l"(r) : "f"(x)); return r;
}
__device__ __forceinline__ ull pk2(float lo, float hi) {
    ull r; asm("mov.b64 %0, {%1, %2};" : "=l"(r) : "f"(lo), "f"(hi)); return r;
}
__device__ __forceinline__ ull fma2(ull a, ull b, ull c) {
    ull r; asm("fma.rn.f32x2 %0, %1, %2, %3;" : "=l"(r) : "l"(a), "l"(b), "l"(c)); return r;
}
__device__ __forceinline__ ull add2(ull a, ull b) {
    ull r; asm("add.rn.f32x2 %0, %1, %2;" : "=l"(r) : "l"(a), "l"(b)); return r;
}

// ---------------------------------------------------------------------------
// K1: relative-position bias MLP
// ---------------------------------------------------------------------------
__device__ __forceinline__ float sgnlog(int d) {
    float l = log1pf(fabsf((float)d));
    return d < 0 ? -l : l;
}

__global__ void bias_kernel(const float* __restrict__ mw1, const float* __restrict__ mb1,
                            const float* __restrict__ mw2, const float* __restrict__ mb2) {
    int t = blockIdx.x * 256 + threadIdx.x;
    if (t >= 4096) return;
    int i = t >> 6, j = t & 63;
    float r0 = sgnlog((i >> 3) - (j >> 3));
    float r1 = sgnlog((i & 7) - (j & 7));
    float a0 = 0.f, a1 = 0.f, a2 = 0.f;
    for (int h = 0; h < 256; h++) {
        float hid = fmaf(r0, mw1[h], fmaf(r1, mw1[256 + h], mb1[h]));
        hid = fmaxf(hid, 0.f);
        a0 = fmaf(hid, mw2[h * 3 + 0], a0);
        a1 = fmaf(hid, mw2[h * 3 + 1], a1);
        a2 = fmaf(hid, mw2[h * 3 + 2], a2);
    }
    g_bias[t]        = a0 + mb2[0];
    g_bias[4096 + t] = a1 + mb2[1];
    g_bias[8192 + t] = a2 + mb2[2];
}

// ---------------------------------------------------------------------------
// K2: conv1x1 96->96 (f32x2 packed). tile = 96 out-ch x 128 pixels (64 pairs)
// smem: s_in2[96][66] ull (50688B) + s_w[96][97] f (37248B) + s_b[96] = 88320B
// ---------------------------------------------------------------------------
struct ConvJob { const float* in; const float* w; const float* bias; float* out; float scale; };

__global__ __launch_bounds__(256, 2)
void conv_kernel(ConvJob j0, ConvJob j1, ConvJob j2, ConvJob j3) {
    ConvJob j = (blockIdx.z == 0) ? j0 : (blockIdx.z == 1) ? j1 : (blockIdx.z == 2) ? j2 : j3;
    extern __shared__ char raw[];
    ull*   s_in2 = (ull*)raw;                 // 96*66 = 6336 ull
    float* s_w   = (float*)(raw + 6336 * 8);  // 96*97 = 9312 f
    float* s_b   = s_w + 9312;                // 96
    int tid = threadIdx.x;
    int bx = blockIdx.x;
    int b = bx >> 9, px0 = (bx & 511) << 7;
    const float* inb = j.in + b * IMG + px0;
    float* outb = j.out + b * IMG + px0;

    for (int l = tid; l < 9216; l += 256) s_w[(l / 96) * 97 + (l % 96)] = j.w[l];
    if (tid < 96) s_b[tid] = j.bias[tid];
    for (int l = tid; l < 6144; l += 256) {
        int c = l >> 6, p2 = l & 63;
        s_in2[c * 66 + p2] = *(const ull*)(inb + c * HW + 2 * p2);
    }
    __syncthreads();

    int og = tid >> 3, pg = tid & 7;   // o = og+32u (u<3); pixel-pair = pg+8v (v<8)
    ull acc[3][8];
    #pragma unroll
    for (int u = 0; u < 3; u++)
        #pragma unroll
        for (int v = 0; v < 8; v++) acc[u][v] = 0ull;

    #pragma unroll 4
    for (int c = 0; c < 96; c++) {
        ull w2[3], pf[8];
        #pragma unroll
        for (int u = 0; u < 3; u++) w2[u] = pk(s_w[(og + 32 * u) * 97 + c]);
        #pragma unroll
        for (int v = 0; v < 8; v++) pf[v] = s_in2[c * 66 + pg + 8 * v];
        #pragma unroll
        for (int u = 0; u < 3; u++)
            #pragma unroll
            for (int v = 0; v < 8; v++) acc[u][v] = fma2(w2[u], pf[v], acc[u][v]);
    }

    ull s2 = pk(j.scale);
    #pragma unroll
    for (int u = 0; u < 3; u++) {
        int o = og + 32 * u;
        ull b2 = pk(s_b[o] * j.scale);
        ull* op = (ull*)(outb + o * HW);
        #pragma unroll
        for (int v = 0; v < 8; v++)
            op[pg + 8 * v] = fma2(acc[u][v], s2, b2);   // (x*scale + b*scale)
    }
}

// ---------------------------------------------------------------------------
// K3: window attention, one block per (window, head). No weights in smem.
// smem floats: s_q[64][33] (0..2112) | s_kT 1056 ull (2112..4224) |
//              s_v2 2112 ull (4224..8448) | s_s[64][66] (8448..12672)
//              s_p2 aliases [0..4224).  Total 50688 B, occupancy 4.
// ---------------------------------------------------------------------------
__global__ __launch_bounds__(256, 4)
void attn_kernel() {
    extern __shared__ float sm[];
    float* s_q  = sm;                       // s_q[n*33+d]
    ull*   s_kT = (ull*)(sm + 2112);        // s_kT[d*33+m2] = {K[2m2][d],K[2m2+1][d]}
    ull*   s_v2 = (ull*)(sm + 4224);        // s_v2[m*33+d]  = {v,v}
    float* s_s  = sm + 8448;                // s_s[n*66+m]
    ull*   s_p2 = (ull*)sm;                 // s_p2[m*33+n2] = {P[2n2][m],P[2n2+1][m]}

    int tid = threadIdx.x;
    int blk = blockIdx.x;
    int h = blk % 3;
    int wid = blk / 3;
    int b = wid >> 10, wy = (wid >> 5) & 31, wx = wid & 31;
    int pixoff = b * IMG + wy * 2048 + wx * 8;
    const float* Qb = g_Q + pixoff + h * 32 * HW;
    const float* Kb = g_K + pixoff + h * 32 * HW;
    const float* Vb = g_V + pixoff + h * 32 * HW;

    // ---- load Q (scalar), K (pair-transposed), V (dup-packed) ----
    for (int l = tid; l < 1024; l += 256) {
        int d = l >> 5, n2 = l & 31;
        int ga = d * HW + (n2 >> 2) * 256 + (n2 & 3) * 2;
        ull qv = *(const ull*)(Qb + ga);
        float2 q; asm("mov.b64 {%0, %1}, %2;" : "=f"(q.x), "=f"(q.y) : "l"(qv));
        s_q[(2 * n2) * 33 + d] = q.x;
        s_q[(2 * n2 + 1) * 33 + d] = q.y;
        s_kT[d * 33 + n2] = *(const ull*)(Kb + ga);
        ull vv = *(const ull*)(Vb + ga);
        float2 v; asm("mov.b64 {%0, %1}, %2;" : "=f"(v.x), "=f"(v.y) : "l"(vv));
        s_v2[(2 * n2) * 33 + d] = pk(v.x);
        s_v2[(2 * n2 + 1) * 33 + d] = pk(v.y);
    }
    __syncthreads();

    // ---- S = Q K^T + bias ----
    {
        int n0 = (tid >> 3) << 1, m2g = tid & 7;   // m2 = m2g+8j (j<4)
        ull acc[2][4];
        #pragma unroll
        for (int i = 0; i < 2; i++)
            #pragma unroll
            for (int jj = 0; jj < 4; jj++) acc[i][jj] = 0ull;
        #pragma unroll 4
        for (int d = 0; d < 32; d++) {
            ull qa = pk(s_q[n0 * 33 + d]);
            ull qb = pk(s_q[n0 * 33 + 33 + d]);
            ull kd[4];
            #pragma unroll
            for (int jj = 0; jj < 4; jj++) kd[jj] = s_kT[d * 33 + m2g + 8 * jj];
            #pragma unroll
            for (int jj = 0; jj < 4; jj++) {
                acc[0][jj] = fma2(qa, kd[jj], acc[0][jj]);
                acc[1][jj] = fma2(qb, kd[jj], acc[1][jj]);
            }
        }
        const ull* bb = (const ull*)(g_bias + h * 4096);
        ull* ss = (ull*)s_s;
        #pragma unroll
        for (int i = 0; i < 2; i++) {
            int n = n0 + i;
            #pragma unroll
            for (int jj = 0; jj < 4; jj++) {
                int m2 = m2g + 8 * jj;
                ss[n * 33 + m2] = add2(acc[i][jj], bb[n * 32 + m2]);
            }
        }
    }
    __syncthreads();

    // ---- softmax: 4 threads per row, 16 cols each, shfl-combine ----
    {
        int row = tid >> 2, q4 = tid & 3;
        float* rp = s_s + row * 66 + q4 * 16;
        float e[16];
        float mx = rp[0];
        #pragma unroll
        for (int k = 1; k < 16; k++) mx = fmaxf(mx, rp[k]);
        mx = fmaxf(mx, __shfl_xor_sync(0xffffffffu, mx, 1));
        mx = fmaxf(mx, __shfl_xor_sync(0xffffffffu, mx, 2));
        float sum = 0.f;
        #pragma unroll
        for (int k = 0; k < 16; k++) { e[k] = __expf(rp[k] - mx); sum += e[k]; }
        sum += __shfl_xor_sync(0xffffffffu, sum, 1);
        sum += __shfl_xor_sync(0xffffffffu, sum, 2);
        float r = 1.f / sum;
        #pragma unroll
        for (int k = 0; k < 16; k++) rp[k] = e[k] * r;
    }
    __syncthreads();

    // ---- transpose-pack P into s_p2 (overwrites s_q/s_kT) ----
    for (int l = tid; l < 2048; l += 256) {
        int m = l >> 5, n2 = l & 31;
        s_p2[m * 33 + n2] = pk2(s_s[(2 * n2) * 66 + m], s_s[(2 * n2 + 1) * 66 + m]);
    }
    __syncthreads();

    // ---- O = P V ----
    {
        int n2 = tid >> 3, dg = tid & 7;   // d = dg+8j (j<4)
        ull acc[4];
        #pragma unroll
        for (int jj = 0; jj < 4; jj++) acc[jj] = 0ull;
        #pragma unroll 4
        for (int m = 0; m < 64; m++) {
            ull p2 = s_p2[m * 33 + n2];
            #pragma unroll
            for (int jj = 0; jj < 4; jj++)
                acc[jj] = fma2(p2, s_v2[m * 33 + dg + 8 * jj], acc[jj]);
        }
        int n0 = 2 * n2;
        float* ob = g_attn + pixoff + (n0 >> 3) * 256 + (n0 & 7);
        #pragma unroll
        for (int jj = 0; jj < 4; jj++) {
            int d = dg + 8 * jj;
            *(ull*)(ob + (h * 32 + d) * HW) = acc[jj];
        }
    }
}

// ---------------------------------------------------------------------------
// K4: depthwise 5x5 (reflect pad) + bias + attn  ->  g_D
// one block per (z, b, c, ytile16): 256 threads, 1 col each x 16 rows
// ---------------------------------------------------------------------------
__global__ __launch_bounds__(256)
void dw_kernel(const float* __restrict__ wdw, const float* __restrict__ bdw,
               const float* __restrict__ wdwa, const float* __restrict__ bdwa) {
    extern __shared__ float st[];           // [20][264] + w[32]
    float* s_wd = st + 20 * 264;
    int z = blockIdx.z;
    const float* Vp = z ? g_aV : g_V;
    const float* wD = z ? wdwa : wdw;
    const float* bD = z ? bdwa : bdw;
    float* Dp = g_D + z * NPIX;

    int bx = blockIdx.x;               // 6144 = 16 * 96 * 4
    int yt = bx & 15;
    int v = bx >> 4;
    int c = v % 96, b = v / 96;
    int y0 = yt << 4;
    int tid = threadIdx.x;
    const float* Vc = Vp + b * IMG + c * HW;

    for (int l = tid; l < 5200; l += 256) {
        int r = l / 260, q = l - r * 260;
        int yy = y0 + r - 2; yy = yy < 0 ? -yy : (yy > 255 ? 510 - yy : yy);
        int xx = q - 2;      xx = xx < 0 ? -xx : (xx > 255 ? 510 - xx : xx);
        st[r * 264 + q] = Vc[yy * 256 + xx];
    }
    if (tid < 25) s_wd[tid] = wD[c * 25 + tid];
    __syncthreads();

    float w[25];
    #pragma unroll
    for (int k = 0; k < 25; k++) w[k] = s_wd[k];
    float bias = __ldg(&bD[c]);

    int col = tid;
    float acc[16];
    #pragma unroll
    for (int r = 0; r < 16; r++) acc[r] = bias;

    #pragma unroll
    for (int rr = 0; rr < 20; rr++) {
        float xv[5];
        #pragma unroll
        for (int dx = 0; dx < 5; dx++) xv[dx] = st[rr * 264 + col + dx];
        #pragma unroll
        for (int dy = 0; dy < 5; dy++) {
            int r = rr - dy;
            if (r >= 0 && r < 16) {
                #pragma unroll
                for (int dx = 0; dx < 5; dx++)
                    acc[r] = fmaf(xv[dx], w[dy * 5 + dx], acc[r]);
            }
        }
    }

    const float* ab = g_attn + b * IMG + c * HW + y0 * 256 + col;
    float* db = Dp + b * IMG + c * HW + y0 * 256 + col;
    #pragma unroll
    for (int r = 0; r < 16; r++)
        db[r * 256] = acc[r] + ab[r * 256];
}

// ---------------------------------------------------------------------------
extern "C" void kernel_launch(void* const* d_in, const int* in_sizes, int n_in,
                              void* d_out, int out_size) {
    const float* vision     = (const float*)d_in[0];
    const float* ass_vision = (const float*)d_in[1];
    const float* wv   = (const float*)d_in[2];
    const float* bv   = (const float*)d_in[3];
    const float* wav  = (const float*)d_in[4];
    const float* bav  = (const float*)d_in[5];
    const float* wqk  = (const float*)d_in[6];
    const float* bqk  = (const float*)d_in[7];
    // d_in[8..9]: waqk/baqk dead (reference bug: aaw unused, ass_attn_out = attn_out)
    const float* wdw  = (const float*)d_in[10];
    const float* bdw  = (const float*)d_in[11];
    const float* wdwa = (const float*)d_in[12];
    const float* bdwa = (const float*)d_in[13];
    const float* wp   = (const float*)d_in[14];
    const float* bp   = (const float*)d_in[15];
    const float* wpa  = (const float*)d_in[16];
    const float* bpa  = (const float*)d_in[17];
    const float* mw1  = (const float*)d_in[18];
    const float* mb1  = (const float*)d_in[19];
    const float* mw2  = (const float*)d_in[20];
    const float* mb2  = (const float*)d_in[21];
    float* out = (float*)d_out;

    float *pV, *paV, *pQ, *pK, *pD;
    cudaGetSymbolAddress((void**)&pV,  g_V);
    cudaGetSymbolAddress((void**)&paV, g_aV);
    cudaGetSymbolAddress((void**)&pQ,  g_Q);
    cudaGetSymbolAddress((void**)&pK,  g_K);
    cudaGetSymbolAddress((void**)&pD,  g_D);

    const int SMEM_CONV = 6336 * 8 + 9312 * 4 + 96 * 4;   // 88320
    const int SMEM_ATTN = 12672 * 4;                       // 50688
    const int SMEM_DW   = (20 * 264 + 32) * 4;             // 21248
    cudaFuncSetAttribute(conv_kernel, cudaFuncAttributeMaxDynamicSharedMemorySize, SMEM_CONV);
    cudaFuncSetAttribute(attn_kernel, cudaFuncAttributeMaxDynamicSharedMemorySize, SMEM_ATTN);
    cudaFuncSetAttribute(dw_kernel,   cudaFuncAttributeMaxDynamicSharedMemorySize, SMEM_DW);

    bias_kernel<<<16, 256>>>(mw1, mb1, mw2, mb2);

    ConvJob jV  = { vision,     wv,          bv,       pV,  1.0f };
    ConvJob jaV = { ass_vision, wav,         bav,      paV, 1.0f };
    ConvJob jQ  = { vision,     wqk,         bqk,      pQ,  SCALE };
    ConvJob jK  = { vision,     wqk + 9216,  bqk + 96, pK,  1.0f };
    conv_kernel<<<dim3(2048, 1, 4), 256, SMEM_CONV>>>(jV, jaV, jQ, jK);

    attn_kernel<<<12288, 256, SMEM_ATTN>>>();

    dw_kernel<<<dim3(6144, 1, 2), 256, SMEM_DW>>>(wdw, bdw, wdwa, bdwa);

    ConvJob jP0 = { pD,        wp,  bp,  out,        1.0f };
    ConvJob jP1 = { pD + NPIX, wpa, bpa, out + NPIX, 1.0f };
    conv_kernel<<<dim3(2048, 1, 2), 256, SMEM_CONV>>>(jP0, jP1, jP0, jP0);
}